// round 2
// baseline (speedup 1.0000x reference)
#include <cuda_runtime.h>
#include <cuda_bf16.h>
#include <math.h>

// ---------------------------------------------------------------------------
// Problem constants
// ---------------------------------------------------------------------------
#define BATCH 4
#define LIN   40960
#define CCH   512
#define T0    8192
#define T1    2048
#define T2    1024
#define T3    512
#define TN    256
#define DMLP  2048

// ---------------------------------------------------------------------------
// Scratch (device globals; no allocation allowed)
// ---------------------------------------------------------------------------
__device__ float g_h0[BATCH * T0 * CCH];      // 64 MB  [b][t][c]
__device__ float g_h1[BATCH * T1 * CCH];      // 16 MB
__device__ float g_h2[BATCH * T2 * CCH];      //  8 MB
__device__ float g_f [BATCH * T3 * CCH];      //  4 MB  (features for MLP + pooling)
__device__ float g_z1[BATCH * T3 * DMLP];     // 16 MB
__device__ float g_z2[BATCH * T3 * DMLP];     // 16 MB
__device__ float g_imp[BATCH * T3];
__device__ float g_cs [BATCH * T3];
__device__ float g_w0t[10 * CCH];
__device__ float g_w1t[CCH * 8 * CCH];        //  8 MB
__device__ float g_w2t[CCH * 4 * CCH];        //  4 MB
__device__ float g_w3t[CCH * 4 * CCH];        //  4 MB

// ---------------------------------------------------------------------------
// Helpers
// ---------------------------------------------------------------------------
__device__ __forceinline__ int refl(int p, int n) {
    return p < 0 ? -p : (p >= n ? 2 * n - 2 - p : p);
}

__device__ __forceinline__ float gelu_exact(float v) {
    return 0.5f * v * (1.f + erff(v * 0.70710678118654752f));
}

// Block-wide (sum, sumsq) reduction. sred must hold >= 64 floats.
__device__ __forceinline__ float2 block_reduce2(float v1, float v2, float* sred) {
    __syncthreads();  // protect sred reuse across calls
    int lane = threadIdx.x & 31, wid = threadIdx.x >> 5;
    int nw = blockDim.x >> 5;
#pragma unroll
    for (int o = 16; o > 0; o >>= 1) {
        v1 += __shfl_down_sync(0xffffffffu, v1, o);
        v2 += __shfl_down_sync(0xffffffffu, v2, o);
    }
    if (lane == 0) { sred[wid] = v1; sred[wid + 32] = v2; }
    __syncthreads();
    if (wid == 0) {
        v1 = (lane < nw) ? sred[lane] : 0.f;
        v2 = (lane < nw) ? sred[lane + 32] : 0.f;
#pragma unroll
        for (int o = 16; o > 0; o >>= 1) {
            v1 += __shfl_down_sync(0xffffffffu, v1, o);
            v2 += __shfl_down_sync(0xffffffffu, v2, o);
        }
        if (lane == 0) { sred[0] = v1; sred[32] = v2; }
    }
    __syncthreads();
    return make_float2(sred[0], sred[32]);
}

// ---------------------------------------------------------------------------
// Weight transpose: w[c][ci][k] -> wt[(ci*KW+k)*512 + c]
// ---------------------------------------------------------------------------
__global__ void k_wtrans(const float* __restrict__ w, float* __restrict__ wt,
                         int CI, int KW, int total) {
    int idx = blockIdx.x * blockDim.x + threadIdx.x;
    if (idx < total) {
        int ck = CI * KW;
        int c = idx / ck;
        int r = idx - c * ck;
        wt[r * CCH + c] = w[idx];
    }
}

// ---------------------------------------------------------------------------
// conv0 (1->512, k=10, s=5, reflect pad 3) + ChannelNorm + ReLU
// grid (T0/8, B), block 512 (one thread per channel)
// ---------------------------------------------------------------------------
__global__ __launch_bounds__(512) void k_conv0(
    const float* __restrict__ x, const float* __restrict__ w0t,
    const float* __restrict__ bias, const float* __restrict__ nw,
    const float* __restrict__ nb, float* __restrict__ out) {
    const int TT = 8, KW = 10, S = 5, PAD = 3;
    const int W = S * (TT - 1) + KW;  // 45
    __shared__ float sx[48];
    __shared__ float sred[64];
    int b = blockIdx.y, t0 = blockIdx.x * TT, c = threadIdx.x;
    if (c < W) {
        int p = refl(S * t0 - PAD + c, LIN);
        sx[c] = x[b * LIN + p];
    }
    __syncthreads();
    float acc[TT];
    float bi = bias[c];
#pragma unroll
    for (int tt = 0; tt < TT; tt++) acc[tt] = bi;
#pragma unroll
    for (int k = 0; k < KW; k++) {
        float w = w0t[k * CCH + c];
#pragma unroll
        for (int tt = 0; tt < TT; tt++) acc[tt] = fmaf(w, sx[S * tt + k], acc[tt]);
    }
    float gw = nw[c], gb = nb[c];
    for (int tt = 0; tt < TT; tt++) {
        float2 s = block_reduce2(acc[tt], acc[tt] * acc[tt], sred);
        float mean = s.x * (1.f / 512.f);
        float var  = (s.y - s.x * s.x * (1.f / 512.f)) * (1.f / 511.f);
        float inv  = rsqrtf(var + 1e-5f);
        float v    = (acc[tt] - mean) * inv * gw + gb;
        out[((size_t)(b * T0 + t0 + tt)) * CCH + c] = fmaxf(v, 0.f);
    }
}

// ---------------------------------------------------------------------------
// Generic fused conv (512->512) + ChannelNorm + ReLU.
// block 256 threads, thread j handles channels j and j+256, TT time-steps.
// Input/output layout [b][t][c].
// ---------------------------------------------------------------------------
template <int KW, int S, int PAD, int TT>
__global__ __launch_bounds__(256) void k_conv(
    const float* __restrict__ xin, int TINv, int TOUTv,
    const float* __restrict__ wt, const float* __restrict__ bias,
    const float* __restrict__ nw, const float* __restrict__ nb,
    float* __restrict__ out) {
    constexpr int W = S * (TT - 1) + KW;
    __shared__ float sx[W * 128];
    __shared__ float sred[64];
    int b = blockIdx.y, t0 = blockIdx.x * TT, j = threadIdx.x;
    int c0 = j, c1 = j + 256;
    float acc0[TT], acc1[TT];
    float bi0 = bias[c0], bi1 = bias[c1];
#pragma unroll
    for (int tt = 0; tt < TT; tt++) { acc0[tt] = bi0; acc1[tt] = bi1; }
    int base = S * t0 - PAD;
    for (int cc = 0; cc < CCH; cc += 128) {
        __syncthreads();
        for (int i = j; i < W * 128; i += 256) {
            int r = i >> 7, ci = i & 127;
            int p = refl(base + r, TINv);
            sx[i] = xin[((size_t)(b * TINv + p)) * CCH + cc + ci];
        }
        __syncthreads();
        for (int ci = 0; ci < 128; ci++) {
            const float* wb = wt + ((size_t)(cc + ci) * KW) * CCH;
#pragma unroll
            for (int k = 0; k < KW; k++) {
                float w0 = wb[k * CCH + c0];
                float w1 = wb[k * CCH + c1];
#pragma unroll
                for (int tt = 0; tt < TT; tt++) {
                    float v = sx[(S * tt + k) * 128 + ci];
                    acc0[tt] = fmaf(w0, v, acc0[tt]);
                    acc1[tt] = fmaf(w1, v, acc1[tt]);
                }
            }
        }
    }
    float g0 = nw[c0], g1 = nw[c1], e0 = nb[c0], e1 = nb[c1];
    for (int tt = 0; tt < TT; tt++) {
        float2 s = block_reduce2(acc0[tt] + acc1[tt],
                                 acc0[tt] * acc0[tt] + acc1[tt] * acc1[tt], sred);
        float mean = s.x * (1.f / 512.f);
        float var  = (s.y - s.x * s.x * (1.f / 512.f)) * (1.f / 511.f);
        float inv  = rsqrtf(var + 1e-5f);
        size_t row = ((size_t)(b * TOUTv + t0 + tt)) * CCH;
        out[row + c0] = fmaxf((acc0[tt] - mean) * inv * g0 + e0, 0.f);
        out[row + c1] = fmaxf((acc1[tt] - mean) * inv * g1 + e1, 0.f);
    }
}

// ---------------------------------------------------------------------------
// Tiled fp32 GEMM (128x128x8, 8x8 per thread) + bias + exact GELU epilogue.
// C[M,N] = gelu(A[M,K] @ B[K,N] + bias)
// ---------------------------------------------------------------------------
__global__ __launch_bounds__(256, 2) void k_gemm_gelu(
    const float* __restrict__ A, const float* __restrict__ Bm,
    const float* __restrict__ bias, float* __restrict__ Cm,
    int M, int N, int K) {
    __shared__ float As[8][128];
    __shared__ float Bs[8][128];
    int tid = threadIdx.x;
    int tx = tid & 15, ty = tid >> 4;
    const float* Ab = A + (size_t)blockIdx.y * 128 * K;
    const float* Bb = Bm + blockIdx.x * 128;
    float acc[8][8];
#pragma unroll
    for (int i = 0; i < 8; i++)
#pragma unroll
        for (int jj = 0; jj < 8; jj++) acc[i][jj] = 0.f;
    int arow = tid >> 1, acol = (tid & 1) * 4;
    int brow = tid >> 5, bcol = (tid & 31) * 4;
    for (int k0 = 0; k0 < K; k0 += 8) {
        float4 av = *(const float4*)(Ab + (size_t)arow * K + k0 + acol);
        float4 bv = *(const float4*)(Bb + (size_t)(k0 + brow) * N + bcol);
        __syncthreads();
        As[acol + 0][arow] = av.x;
        As[acol + 1][arow] = av.y;
        As[acol + 2][arow] = av.z;
        As[acol + 3][arow] = av.w;
        *(float4*)(&Bs[brow][bcol]) = bv;
        __syncthreads();
#pragma unroll
        for (int kk = 0; kk < 8; kk++) {
            float a[8], bb[8];
            *(float4*)(a)      = *(const float4*)(&As[kk][ty * 8]);
            *(float4*)(a + 4)  = *(const float4*)(&As[kk][ty * 8 + 4]);
            *(float4*)(bb)     = *(const float4*)(&Bs[kk][tx * 8]);
            *(float4*)(bb + 4) = *(const float4*)(&Bs[kk][tx * 8 + 4]);
#pragma unroll
            for (int i = 0; i < 8; i++)
#pragma unroll
                for (int jj = 0; jj < 8; jj++)
                    acc[i][jj] = fmaf(a[i], bb[jj], acc[i][jj]);
        }
    }
    int m0 = blockIdx.y * 128 + ty * 8, n0 = blockIdx.x * 128 + tx * 8;
    float bv8[8];
#pragma unroll
    for (int jj = 0; jj < 8; jj++) bv8[jj] = bias[n0 + jj];
#pragma unroll
    for (int i = 0; i < 8; i++) {
#pragma unroll
        for (int jj = 0; jj < 8; jj++) acc[i][jj] = gelu_exact(acc[i][jj] + bv8[jj]);
        *(float4*)(Cm + (size_t)(m0 + i) * N + n0) =
            make_float4(acc[i][0], acc[i][1], acc[i][2], acc[i][3]);
        *(float4*)(Cm + (size_t)(m0 + i) * N + n0 + 4) =
            make_float4(acc[i][4], acc[i][5], acc[i][6], acc[i][7]);
    }
}

// ---------------------------------------------------------------------------
// MLP head: imp = sigmoid(z2 @ w3 + b3) + 1e-5.  One warp per row.
// ---------------------------------------------------------------------------
__global__ __launch_bounds__(256) void k_mlp3(
    const float* __restrict__ z2, const float* __restrict__ w3,
    const float* __restrict__ b3, float* __restrict__ imp) {
    int row = blockIdx.x * 8 + (threadIdx.x >> 5);
    int lane = threadIdx.x & 31;
    const float* zr = z2 + (size_t)row * DMLP;
    float s = 0.f;
    for (int i = lane; i < DMLP; i += 32) s = fmaf(zr[i], w3[i], s);
#pragma unroll
    for (int o = 16; o > 0; o >>= 1) s += __shfl_down_sync(0xffffffffu, s, o);
    if (lane == 0) imp[row] = 1.f / (1.f + expf(-(s + b3[0]))) + 1e-5f;
}

// ---------------------------------------------------------------------------
// Normalize importance + inclusive cumsum. One block per batch (512 threads).
// cs[t] = cumsum(imp)[t] * 256 / sum(imp)
// ---------------------------------------------------------------------------
__global__ __launch_bounds__(512) void k_scan(const float* __restrict__ imp,
                                              float* __restrict__ cs) {
    __shared__ float sa[512], sb[512];
    int b = blockIdx.x, t = threadIdx.x;
    sa[t] = imp[b * T3 + t];
    __syncthreads();
    float* src = sa;
    float* dst = sb;
    for (int off = 1; off < 512; off <<= 1) {
        float v = src[t] + ((t >= off) ? src[t - off] : 0.f);
        dst[t] = v;
        __syncthreads();
        float* tmp = src; src = dst; dst = tmp;
    }
    float scale = 256.f / src[511];
    cs[b * T3 + t] = src[t] * scale;
}

// ---------------------------------------------------------------------------
// Smartpool warp + final ChannelNorm + ReLU.
// pooled[b,n,c] = sum_t (d(cs[t],n) - d(cs[t-1],n)) * f[b,t,c]
// where d(x,n) = clamp01(x-n) for n<TN-1, max(x-n,0) for n=TN-1 (ref padding).
// grid (TN, B), block 512 (one thread per channel). Output [B][C][TN].
// ---------------------------------------------------------------------------
__global__ __launch_bounds__(512) void k_pool(
    const float* __restrict__ f, const float* __restrict__ cs,
    const float* __restrict__ nw, const float* __restrict__ nb,
    float* __restrict__ out) {
    __shared__ float scs[513];
    __shared__ float sred[64];
    int b = blockIdx.y, n = blockIdx.x, c = threadIdx.x;
    if (c == 0) scs[0] = 0.f;
    scs[c + 1] = cs[b * T3 + c];
    __syncthreads();
    float fn = (float)n;
    bool lastn = (n == TN - 1);
    // contiguous active range: cs monotone increasing
    int lo;
    {
        int a = 0, e = 512;
        while (a < e) { int m = (a + e) >> 1; if (scs[m + 1] > fn) e = m; else a = m + 1; }
        lo = a;
    }
    int hi = 512;
    if (!lastn) {
        int a = 0, e = 512;
        while (a < e) { int m = (a + e) >> 1; if (scs[m] < fn + 1.f) a = m + 1; else e = m; }
        hi = a;
    }
    float acc = 0.f;
    for (int t = lo; t < hi; t++) {
        float x1 = scs[t + 1] - fn, x0 = scs[t] - fn;
        float d1 = lastn ? fmaxf(x1, 0.f) : fminf(fmaxf(x1, 0.f), 1.f);
        float d0 = lastn ? fmaxf(x0, 0.f) : fminf(fmaxf(x0, 0.f), 1.f);
        acc = fmaf(d1 - d0, f[((size_t)(b * T3 + t)) * CCH + c], acc);
    }
    float2 s = block_reduce2(acc, acc * acc, sred);
    float mean = s.x * (1.f / 512.f);
    float var  = (s.y - s.x * s.x * (1.f / 512.f)) * (1.f / 511.f);
    float inv  = rsqrtf(var + 1e-5f);
    float v    = (acc - mean) * inv * nw[c] + nb[c];
    out[((size_t)(b * CCH + c)) * TN + n] = fmaxf(v, 0.f);
}

// ---------------------------------------------------------------------------
// Launch
// ---------------------------------------------------------------------------
extern "C" void kernel_launch(void* const* d_in, const int* in_sizes, int n_in,
                              void* d_out, int out_size) {
    (void)in_sizes; (void)n_in; (void)out_size;
    const float* x   = (const float*)d_in[0];
    const float* c0w = (const float*)d_in[1];
    const float* c0b = (const float*)d_in[2];
    const float* c1w = (const float*)d_in[3];
    const float* c1b = (const float*)d_in[4];
    const float* c2w = (const float*)d_in[5];
    const float* c2b = (const float*)d_in[6];
    const float* c3w = (const float*)d_in[7];
    const float* c3b = (const float*)d_in[8];
    const float* w1  = (const float*)d_in[9];
    const float* b1  = (const float*)d_in[10];
    const float* w2  = (const float*)d_in[11];
    const float* b2  = (const float*)d_in[12];
    const float* w3  = (const float*)d_in[13];
    const float* b3  = (const float*)d_in[14];
    const float* n0w = (const float*)d_in[15];
    const float* n0b = (const float*)d_in[16];
    const float* n1w = (const float*)d_in[17];
    const float* n1b = (const float*)d_in[18];
    const float* n2w = (const float*)d_in[19];
    const float* n2b = (const float*)d_in[20];
    const float* n3w = (const float*)d_in[21];
    const float* n3b = (const float*)d_in[22];
    const float* n4w = (const float*)d_in[23];
    const float* n4b = (const float*)d_in[24];
    float* out = (float*)d_out;

    float *p_h0, *p_h1, *p_h2, *p_f, *p_z1, *p_z2, *p_imp, *p_cs;
    float *p_w0t, *p_w1t, *p_w2t, *p_w3t;
    cudaGetSymbolAddress((void**)&p_h0,  g_h0);
    cudaGetSymbolAddress((void**)&p_h1,  g_h1);
    cudaGetSymbolAddress((void**)&p_h2,  g_h2);
    cudaGetSymbolAddress((void**)&p_f,   g_f);
    cudaGetSymbolAddress((void**)&p_z1,  g_z1);
    cudaGetSymbolAddress((void**)&p_z2,  g_z2);
    cudaGetSymbolAddress((void**)&p_imp, g_imp);
    cudaGetSymbolAddress((void**)&p_cs,  g_cs);
    cudaGetSymbolAddress((void**)&p_w0t, g_w0t);
    cudaGetSymbolAddress((void**)&p_w1t, g_w1t);
    cudaGetSymbolAddress((void**)&p_w2t, g_w2t);
    cudaGetSymbolAddress((void**)&p_w3t, g_w3t);

    // weight transposes
    k_wtrans<<<(10 * CCH + 255) / 256, 256>>>(c0w, p_w0t, 1, 10, 10 * CCH);
    k_wtrans<<<(CCH * 8 * CCH) / 256, 256>>>(c1w, p_w1t, CCH, 8, CCH * 8 * CCH);
    k_wtrans<<<(CCH * 4 * CCH) / 256, 256>>>(c2w, p_w2t, CCH, 4, CCH * 4 * CCH);
    k_wtrans<<<(CCH * 4 * CCH) / 256, 256>>>(c3w, p_w3t, CCH, 4, CCH * 4 * CCH);

    // encoder
    k_conv0<<<dim3(T0 / 8, BATCH), 512>>>(x, p_w0t, c0b, n0w, n0b, p_h0);
    k_conv<8, 4, 2, 16><<<dim3(T1 / 16, BATCH), 256>>>(p_h0, T0, T1, p_w1t, c1b, n1w, n1b, p_h1);
    k_conv<4, 2, 1, 16><<<dim3(T2 / 16, BATCH), 256>>>(p_h1, T1, T2, p_w2t, c2b, n2w, n2b, p_h2);
    k_conv<4, 2, 1, 8><<<dim3(T3 / 8, BATCH), 256>>>(p_h2, T2, T3, p_w3t, c3b, n3w, n3b, p_f);

    // importance MLP
    k_gemm_gelu<<<dim3(DMLP / 128, (BATCH * T3) / 128), 256>>>(p_f, w1, b1, p_z1,
                                                               BATCH * T3, DMLP, CCH);
    k_gemm_gelu<<<dim3(DMLP / 128, (BATCH * T3) / 128), 256>>>(p_z1, w2, b2, p_z2,
                                                               BATCH * T3, DMLP, DMLP);
    k_mlp3<<<(BATCH * T3) / 8, 256>>>(p_z2, w3, b3, p_imp);
    k_scan<<<BATCH, 512>>>(p_imp, p_cs);

    // smartpool warp + final norm
    k_pool<<<dim3(TN, BATCH), 512>>>(p_f, p_cs, n4w, n4b, out);
}